// round 15
// baseline (speedup 1.0000x reference)
#include <cuda_runtime.h>
#include <cuda_fp16.h>
#include <math.h>

#define N_NODES 8192
#define N_EDGES 32768
#define FN 32
#define FE 16
#define H 73
#define HH (H*H)            // 5329
#define KP 80               // padded K (5 x k16)
#define TW 5402             // T2 logical row width = 73*74
#define TWP 5504            // padded pitch (43*128)
#define GGW 512             // fused GRU weight width (4 x 128)
#define NB 64
#define T_MP 3
#define T_S2S 12

// ---------------- device scratch ----------------
__device__ float g_h[N_NODES * H];
__device__ __half g_h16[N_NODES * KP];
__device__ float g_RH[N_EDGES * H];
__device__ float g_agg[N_NODES * H];
__device__ __half g_T2[(size_t)N_NODES * TWP];    // 90 MB fp16
__device__ __half g_W2e[KP * TWP];
__device__ __half g_Wgru[160 * GGW];              // interleaved block-diag GRU weights
__device__ int g_off[N_NODES + 1];
__device__ int g_cur[N_NODES];
__device__ int g_eord[N_EDGES];
__device__ int g_tgtS[N_EDGES];

__device__ __forceinline__ float sigf(float x) { return 1.0f / (1.0f + expf(-x)); }

__device__ __forceinline__ void ldsm_x4(unsigned &r0, unsigned &r1, unsigned &r2, unsigned &r3, unsigned addr) {
    asm volatile("ldmatrix.sync.aligned.m8n8.x4.shared.b16 {%0,%1,%2,%3},[%4];"
                 : "=r"(r0), "=r"(r1), "=r"(r2), "=r"(r3) : "r"(addr));
}
__device__ __forceinline__ void ldsm_x4t(unsigned &r0, unsigned &r1, unsigned &r2, unsigned &r3, unsigned addr) {
    asm volatile("ldmatrix.sync.aligned.m8n8.x4.trans.shared.b16 {%0,%1,%2,%3},[%4];"
                 : "=r"(r0), "=r"(r1), "=r"(r2), "=r"(r3) : "r"(addr));
}
__device__ __forceinline__ void mma16816(float* d, const unsigned* a, unsigned b0, unsigned b1) {
    asm volatile("mma.sync.aligned.m16n8k16.row.col.f32.f16.f16.f32 "
                 "{%0,%1,%2,%3},{%4,%5,%6,%7},{%8,%9},{%0,%1,%2,%3};"
                 : "+f"(d[0]), "+f"(d[1]), "+f"(d[2]), "+f"(d[3])
                 : "r"(a[0]), "r"(a[1]), "r"(a[2]), "r"(a[3]), "r"(b0), "r"(b1));
}

// ---------------- k_prep: prepW2 (blocks 0..72) + h0 + RH ----------------
#define NB_H0 ((N_NODES * KP) / 256)      // 2560
#define NB_RH ((N_EDGES * H) / 256)       // 9344
__global__ __launch_bounds__(256) void k_prep(const float* __restrict__ nf,
                                              const float* __restrict__ Win,
                                              const float* __restrict__ bin,
                                              const float* __restrict__ ef,
                                              const float* __restrict__ W1,
                                              const float* __restrict__ b1,
                                              const float* __restrict__ W2,
                                              const float* __restrict__ b2) {
    __shared__ float tile[74 * 73];
    int b = blockIdx.x;
    int tid = threadIdx.x;
    if (b < 73) {
        int i = b;
        for (int idx = tid; idx < 74 * 73; idx += 256) {
            int kk = idx / 73, j = idx % 73;
            tile[idx] = (kk < H) ? W2[(size_t)kk * HH + i * H + j] : b2[i * H + j];
        }
        __syncthreads();
        for (int idx = tid; idx < 73 * 74; idx += 256) {
            int j = idx / 74, kk = idx % 74;
            g_W2e[(size_t)j * TWP + i * 74 + kk] = __float2half(tile[kk * 73 + j]);
        }
        const int PAD1 = 7 * TWP, PADT = PAD1 + 73 * 102;
        for (int p = b * 256 + tid; p < PADT; p += 73 * 256) {
            int j, c;
            if (p < PAD1) { j = 73 + p / TWP; c = p % TWP; }
            else { int q = p - PAD1; j = q / 102; c = TW + q % 102; }
            g_W2e[(size_t)j * TWP + c] = __float2half(0.0f);
        }
    } else if (b < 73 + NB_H0) {
        int idx = (b - 73) * 256 + tid;
        if (idx < N_NODES * H) g_agg[idx] = 0.0f;
        int n = idx / KP, c = idx % KP;
        if (c >= H) { g_h16[idx] = __float2half(0.0f); return; }
        const float* x = nf + n * FN;
        float acc = bin[c];
#pragma unroll
        for (int k = 0; k < FN; k++) acc += x[k] * Win[k * H + c];
        g_h[n * H + c] = acc;
        g_h16[idx] = __float2half(acc);
    } else {
        int idx = (b - 73 - NB_H0) * 256 + tid;
        int e = idx / H, c = idx % H;
        const float* x = ef + e * FE;
        float acc = b1[c];
#pragma unroll
        for (int k = 0; k < FE; k++) acc += x[k] * W1[k * H + c];
        g_RH[idx] = fmaxf(acc, 0.0f);
    }
}

// ---------------- scan with in-kernel histogram ----------------
__global__ __launch_bounds__(1024) void k_scan(const int* __restrict__ Esrc) {
    __shared__ int hist[N_NODES];
    __shared__ int sm_[1024];
    int tid = threadIdx.x;
    for (int i = tid; i < N_NODES; i += 1024) hist[i] = 0;
    __syncthreads();
    for (int e = tid; e < N_EDGES; e += 1024) atomicAdd(&hist[Esrc[e]], 1);
    __syncthreads();
    int base = tid * 8;
    int v[8], s = 0;
#pragma unroll
    for (int i = 0; i < 8; i++) { v[i] = hist[base + i]; s += v[i]; }
    sm_[tid] = s;
    __syncthreads();
    for (int off = 1; off < 1024; off <<= 1) {
        int t = (tid >= off) ? sm_[tid - off] : 0;
        __syncthreads();
        sm_[tid] += t;
        __syncthreads();
    }
    int run = sm_[tid] - s;
#pragma unroll
    for (int i = 0; i < 8; i++) {
        g_off[base + i] = run;
        g_cur[base + i] = run;
        run += v[i];
    }
    if (tid == 1023) g_off[N_NODES] = run;
}

// ---------------- misc: scatter edges + interleaved block-diag GRU weights -------
__global__ void k_misc(const int* __restrict__ Esrc, const int* __restrict__ Etgt,
                       const float* __restrict__ Wih, const float* __restrict__ Whh) {
    int idx = blockIdx.x * blockDim.x + threadIdx.x;
    if (idx < N_EDGES) {
        int p = atomicAdd(&g_cur[Esrc[idx]], 1);
        g_eord[p] = idx;
        g_tgtS[p] = Etgt[idx];
    }
    if (idx < 160 * GGW) {
        int k = idx >> 9, cc = idx & (GGW - 1);
        int t = cc >> 7, within = cc & 127;
        int j = within / 6, slot = within % 6;
        int c = 21 * t + j;
        float v = 0.0f;
        if (within < 126 && c < H) {
            if (slot == 0 && k < H)            v = Wih[(size_t)c * H + k];
            else if (slot == 2 && k < H)       v = Wih[(size_t)(H + c) * H + k];
            else if (slot == 4 && k < H)       v = Wih[(size_t)(2 * H + c) * H + k];
            else if (slot == 1 && k >= KP && k < KP + H) v = Whh[(size_t)c * H + (k - KP)];
            else if (slot == 3 && k >= KP && k < KP + H) v = Whh[(size_t)(H + c) * H + (k - KP)];
            else if (slot == 5 && k >= KP && k < KP + H) v = Whh[(size_t)(2 * H + c) * H + (k - KP)];
        }
        g_Wgru[idx] = __float2half(v);
    }
}

// ---------------- T2 GEMM: 128x64 tile, 3 blocks/SM target ----------------
// T2[M,TWP] = h16[M,80] @ W2e[80,TWP], fp16 out, smem-staged coalesced stores.
__global__ __launch_bounds__(256, 3) void k_tgemm(const __half* __restrict__ A) {
    __shared__ __align__(16) __half sm_u[17024];   // As 128*88 + Bs 80*72 = 34048 B
    __half* As = sm_u;                 // [128][88]
    __half* Bs = sm_u + 128 * 88;      // [80][72]
    __half* Cs = sm_u;                 // [128][72] alias (18432 B)
    int tid = threadIdx.x;
    int m0 = blockIdx.y * 128;
    int n0 = blockIdx.x * 64;

    for (int idx = tid; idx < 1280; idx += 256) {
        int r = idx / 10, c = idx % 10;
        *reinterpret_cast<uint4*>(&As[r * 88 + c * 8]) =
            *reinterpret_cast<const uint4*>(A + (size_t)(m0 + r) * KP + c * 8);
    }
    for (int idx = tid; idx < 640; idx += 256) {
        int k = idx >> 3, c = idx & 7;
        *reinterpret_cast<uint4*>(&Bs[k * 72 + c * 8]) =
            *reinterpret_cast<const uint4*>(g_W2e + (size_t)k * TWP + n0 + c * 8);
    }
    __syncthreads();

    int wid = tid >> 5, lane = tid & 31;
    int wm0 = (wid & 3) * 32;          // 4 warps along M
    int wn0 = (wid >> 2) * 32;         // 2 warps along N

    float acc[2][4][4];
#pragma unroll
    for (int i = 0; i < 2; i++)
#pragma unroll
        for (int j = 0; j < 4; j++)
#pragma unroll
            for (int q = 0; q < 4; q++) acc[i][j][q] = 0.0f;

    unsigned a_base = (unsigned)__cvta_generic_to_shared(As);
    unsigned b_base = (unsigned)__cvta_generic_to_shared(Bs);
    int lr = lane & 15, lc = (lane >> 4) * 8;

#pragma unroll
    for (int ks = 0; ks < 5; ks++) {
        int k0 = ks * 16;
        unsigned af[2][4];
#pragma unroll
        for (int mi = 0; mi < 2; mi++) {
            unsigned addr = a_base + (unsigned)(((wm0 + mi * 16 + lr) * 88 + k0 + lc) * 2);
            ldsm_x4(af[mi][0], af[mi][1], af[mi][2], af[mi][3], addr);
        }
        unsigned bf[2][4];
#pragma unroll
        for (int nj = 0; nj < 2; nj++) {
            unsigned addr = b_base + (unsigned)(((k0 + lr) * 72 + wn0 + nj * 16 + lc) * 2);
            ldsm_x4t(bf[nj][0], bf[nj][1], bf[nj][2], bf[nj][3], addr);
        }
#pragma unroll
        for (int mi = 0; mi < 2; mi++)
#pragma unroll
            for (int nj = 0; nj < 2; nj++) {
                mma16816(acc[mi][2 * nj], af[mi], bf[nj][0], bf[nj][1]);
                mma16816(acc[mi][2 * nj + 1], af[mi], bf[nj][2], bf[nj][3]);
            }
    }
    __syncthreads();

    int gr = lane >> 2, gc = (lane & 3) * 2;
#pragma unroll
    for (int mi = 0; mi < 2; mi++) {
#pragma unroll
        for (int nj8 = 0; nj8 < 4; nj8++) {
            int col = wn0 + nj8 * 8 + gc;
#pragma unroll
            for (int rr = 0; rr < 2; rr++) {
                int row = wm0 + mi * 16 + gr + rr * 8;
                *reinterpret_cast<__half2*>(&Cs[row * 72 + col]) =
                    __floats2half2_rn(acc[mi][nj8][rr * 2], acc[mi][nj8][rr * 2 + 1]);
            }
        }
    }
    __syncthreads();

    // coalesced STG.128: 128 rows x 8 uint4
    for (int idx = tid; idx < 1024; idx += 256) {
        int r = idx >> 3, c = idx & 7;
        *reinterpret_cast<uint4*>(g_T2 + (size_t)(m0 + r) * TWP + n0 + c * 8) =
            *reinterpret_cast<const uint4*>(&Cs[r * 72 + c * 8]);
    }
}

// ---------------- messages: block per src, transposed-RH broadcast inner loop ----
__global__ __launch_bounds__(128) void k_msg2() {
    int src = blockIdx.x;
    int s0 = g_off[src], s1 = g_off[src + 1];
    if (s0 == s1) return;
    __shared__ __align__(16) __half tvs[5408];
    __shared__ __align__(16) float rh_t[74][8];
    __shared__ int tgts[8];
    int tid = threadIdx.x;

    {
        const uint4* trow = reinterpret_cast<const uint4*>(g_T2 + (size_t)src * TWP);
        uint4* dst = reinterpret_cast<uint4*>(tvs);
        for (int q = tid; q < 676; q += 128) dst[q] = trow[q];
    }

    for (int base = s0; base < s1; base += 8) {
        int ne = min(8, s1 - base);
        for (int idx = tid; idx < 8 * 74; idx += 128) {
            int e = idx & 7, k = idx >> 3;
            float v = 0.0f;
            if (e < ne) v = (k < H) ? g_RH[(size_t)g_eord[base + e] * H + k] : 1.0f;
            rh_t[k][e] = v;
        }
        if (tid < 8) tgts[tid] = (tid < ne) ? g_tgtS[base + tid] : 0;
        __syncthreads();
        if (tid < H) {
            const __half2* tp = reinterpret_cast<const __half2*>(tvs + tid * 74);
            float a0 = 0, a1 = 0, a2 = 0, a3 = 0, a4 = 0, a5 = 0, a6 = 0, a7 = 0;
#pragma unroll
            for (int k2 = 0; k2 < 37; k2++) {
                float2 tf = __half22float2(tp[k2]);
                float4 r0a = *reinterpret_cast<const float4*>(&rh_t[2 * k2][0]);
                float4 r0b = *reinterpret_cast<const float4*>(&rh_t[2 * k2][4]);
                float4 r1a = *reinterpret_cast<const float4*>(&rh_t[2 * k2 + 1][0]);
                float4 r1b = *reinterpret_cast<const float4*>(&rh_t[2 * k2 + 1][4]);
                a0 += tf.x * r0a.x + tf.y * r1a.x;
                a1 += tf.x * r0a.y + tf.y * r1a.y;
                a2 += tf.x * r0a.z + tf.y * r1a.z;
                a3 += tf.x * r0a.w + tf.y * r1a.w;
                a4 += tf.x * r0b.x + tf.y * r1b.x;
                a5 += tf.x * r0b.y + tf.y * r1b.y;
                a6 += tf.x * r0b.z + tf.y * r1b.z;
                a7 += tf.x * r0b.w + tf.y * r1b.w;
            }
            atomicAdd(&g_agg[(size_t)tgts[0] * H + tid], a0);
            if (1 < ne) atomicAdd(&g_agg[(size_t)tgts[1] * H + tid], a1);
            if (2 < ne) atomicAdd(&g_agg[(size_t)tgts[2] * H + tid], a2);
            if (3 < ne) atomicAdd(&g_agg[(size_t)tgts[3] * H + tid], a3);
            if (4 < ne) atomicAdd(&g_agg[(size_t)tgts[4] * H + tid], a4);
            if (5 < ne) atomicAdd(&g_agg[(size_t)tgts[5] * H + tid], a5);
            if (6 < ne) atomicAdd(&g_agg[(size_t)tgts[6] * H + tid], a6);
            if (7 < ne) atomicAdd(&g_agg[(size_t)tgts[7] * H + tid], a7);
        }
        __syncthreads();
    }
}

// ---------------- fused GRU: gates GEMM (K=160) + pointwise epilogue --------------
__global__ __launch_bounds__(256) void k_gruf(const float* __restrict__ bih,
                                              const float* __restrict__ bhh) {
    extern __shared__ __half sh[];
    __half* As = sh;                  // [128][168]
    __half* Bs = sh + 128 * 168;      // [160][136]
    float* Cs = reinterpret_cast<float*>(sh);   // [128][132] alias
    int tid = threadIdx.x;
    int nt = blockIdx.x;
    int m0 = blockIdx.y * 128;
    int n0 = nt * 128;

    for (int idx = tid; idx < 128 * KP; idx += 256) {
        int r = idx / KP, c = idx - r * KP;
        As[r * 168 + c] = __float2half((c < H) ? g_agg[(size_t)(m0 + r) * H + c] : 0.0f);
    }
    for (int idx = tid; idx < 128 * 10; idx += 256) {
        int r = idx / 10, q = idx - r * 10;
        *reinterpret_cast<uint4*>(&As[r * 168 + KP + q * 8]) =
            *reinterpret_cast<const uint4*>(g_h16 + (size_t)(m0 + r) * KP + q * 8);
    }
    for (int idx = tid; idx < 160 * 16; idx += 256) {
        int k = idx >> 4, c = idx & 15;
        *reinterpret_cast<uint4*>(&Bs[k * 136 + c * 8]) =
            *reinterpret_cast<const uint4*>(g_Wgru + (size_t)k * GGW + n0 + c * 8);
    }
    __syncthreads();

    int wid = tid >> 5, lane = tid & 31;
    int wm0 = (wid & 3) * 32;
    int wn0 = (wid >> 2) * 64;

    float acc[2][8][4];
#pragma unroll
    for (int i = 0; i < 2; i++)
#pragma unroll
        for (int j = 0; j < 8; j++)
#pragma unroll
            for (int q = 0; q < 4; q++) acc[i][j][q] = 0.0f;

    unsigned a_base = (unsigned)__cvta_generic_to_shared(As);
    unsigned b_base = (unsigned)__cvta_generic_to_shared(Bs);
    int lr = lane & 15, lc = (lane >> 4) * 8;

#pragma unroll
    for (int ks = 0; ks < 10; ks++) {
        int k0 = ks * 16;
        unsigned af[2][4];
#pragma unroll
        for (int mi = 0; mi < 2; mi++) {
            unsigned addr = a_base + (unsigned)(((wm0 + mi * 16 + lr) * 168 + k0 + lc) * 2);
            ldsm_x4(af[mi][0], af[mi][1], af[mi][2], af[mi][3], addr);
        }
        unsigned bf[4][4];
#pragma unroll
        for (int nj = 0; nj < 4; nj++) {
            unsigned addr = b_base + (unsigned)(((k0 + lr) * 136 + wn0 + nj * 16 + lc) * 2);
            ldsm_x4t(bf[nj][0], bf[nj][1], bf[nj][2], bf[nj][3], addr);
        }
#pragma unroll
        for (int mi = 0; mi < 2; mi++)
#pragma unroll
            for (int nj = 0; nj < 4; nj++) {
                mma16816(acc[mi][2 * nj], af[mi], bf[nj][0], bf[nj][1]);
                mma16816(acc[mi][2 * nj + 1], af[mi], bf[nj][2], bf[nj][3]);
            }
    }
    __syncthreads();

    int gr = lane >> 2, gc = (lane & 3) * 2;
#pragma unroll
    for (int mi = 0; mi < 2; mi++) {
#pragma unroll
        for (int nj8 = 0; nj8 < 8; nj8++) {
            int col = wn0 + nj8 * 8 + gc;
#pragma unroll
            for (int rr = 0; rr < 2; rr++) {
                int row = wm0 + mi * 16 + gr + rr * 8;
                *reinterpret_cast<float2*>(&Cs[row * 132 + col]) =
                    make_float2(acc[mi][nj8][rr * 2], acc[mi][nj8][rr * 2 + 1]);
            }
        }
    }
    __syncthreads();

    int ch0 = 21 * nt;
    int nch = min(21, H - ch0);
    for (int idx = tid; idx < 128 * nch; idx += 256) {
        int r = idx / nch, j = idx - r * nch;
        int c = ch0 + j;
        const float* gbase = &Cs[r * 132 + 6 * j];
        float ir = gbase[0], hr = gbase[1], iz = gbase[2];
        float hz = gbase[3], inn = gbase[4], hn = gbase[5];
        float rg = sigf(ir + hr + bih[c] + bhh[c]);
        float z  = sigf(iz + hz + bih[H + c] + bhh[H + c]);
        float nn = tanhf(inn + bih[2 * H + c] + rg * (hn + bhh[2 * H + c]));
        size_t n = (size_t)(m0 + r);
        float hv = (1.0f - z) * nn + z * g_h[n * H + c];
        g_h[n * H + c] = hv;
        g_h16[n * KP + c] = __float2half(hv);
        g_agg[n * H + c] = 0.0f;
    }
}

// ---------------- Set2Set ----------------
#define EVMAX 2048
__global__ __launch_bounds__(256) void k_s2s(const float* __restrict__ Wih,
                                             const float* __restrict__ Whh,
                                             const float* __restrict__ bih,
                                             const float* __restrict__ bhh,
                                             const float* __restrict__ Wout,
                                             const float* __restrict__ bout,
                                             const int* __restrict__ batch,
                                             float* __restrict__ out) {
    extern __shared__ float sm[];
    float* Wa    = sm;
    float* Wb    = Wa + 292 * 73;
    float* bias  = Wb + 292 * 73;
    float* gates = bias + 292;
    float* hh    = gates + 292;
    float* cc    = hh + 73;
    float* rr    = cc + 73;
    float* rsum  = rr + 73;
    float* ev    = rsum + 73;
    float* red   = ev + EVMAX;

    int tid = threadIdx.x;
    int b = blockIdx.x;

    for (int i = tid; i < 292 * 73; i += 256) {
        int g = i / 73, k = i % 73;
        Wa[i] = Wih[(size_t)g * 146 + k] + Whh[(size_t)g * 73 + k];
        Wb[i] = Wih[(size_t)g * 146 + 73 + k];
    }
    for (int i = tid; i < 292; i += 256) bias[i] = bih[i] + bhh[i];
    if (tid < H) { hh[tid] = 0.0f; cc[tid] = 0.0f; rr[tid] = 0.0f; }

    int lo = 0, hi = N_NODES;
    while (lo < hi) { int mid = (lo + hi) >> 1; if (batch[mid] < b) lo = mid + 1; else hi = mid; }
    int s0 = lo;
    hi = N_NODES;
    while (lo < hi) { int mid = (lo + hi) >> 1; if (batch[mid] < b + 1) lo = mid + 1; else hi = mid; }
    int len = lo - s0;
    if (len > EVMAX) len = EVMAX;
    __syncthreads();

    int lane = tid & 31, w = tid >> 5;

    for (int t = 0; t < T_S2S; t++) {
        for (int g = tid; g < 292; g += 256) {
            const float* wa = Wa + g * 73;
            const float* wb = Wb + g * 73;
            float acc = bias[g];
            for (int k = 0; k < H; k++) acc += hh[k] * wa[k] + rr[k] * wb[k];
            gates[g] = acc;
        }
        __syncthreads();
        if (tid < H) {
            float ig = gates[tid], fg = gates[H + tid], gg = gates[2 * H + tid], og = gates[3 * H + tid];
            float c2 = sigf(fg) * cc[tid] + sigf(ig) * tanhf(gg);
            cc[tid] = c2;
            hh[tid] = sigf(og) * tanhf(c2);
        }
        __syncthreads();

        if (len > 0) {
            for (int n = w; n < len; n += 8) {
                const float* hrow = g_h + (size_t)(s0 + n) * H;
                float acc = 0.0f;
                for (int c = lane; c < H; c += 32) acc += hrow[c] * hh[c];
#pragma unroll
                for (int o = 16; o; o >>= 1) acc += __shfl_down_sync(0xffffffffu, acc, o);
                if (lane == 0) ev[n] = acc;
            }
            __syncthreads();
            float m = -INFINITY;
            for (int n = tid; n < len; n += 256) m = fmaxf(m, ev[n]);
#pragma unroll
            for (int o = 16; o; o >>= 1) m = fmaxf(m, __shfl_xor_sync(0xffffffffu, m, o));
            if (lane == 0) red[w] = m;
            __syncthreads();
            if (tid == 0) {
                float mm = red[0];
                for (int i = 1; i < 8; i++) mm = fmaxf(mm, red[i]);
                red[32] = mm;
            }
            __syncthreads();
            m = red[32];
            float s = 0.0f;
            for (int n = tid; n < len; n += 256) { float a = expf(ev[n] - m); ev[n] = a; s += a; }
#pragma unroll
            for (int o = 16; o; o >>= 1) s += __shfl_xor_sync(0xffffffffu, s, o);
            if (lane == 0) red[w] = s;
            __syncthreads();
            if (tid == 0) {
                float ss = 0.0f;
                for (int i = 0; i < 8; i++) ss += red[i];
                red[33] = ss;
            }
            __syncthreads();
            float inv = 1.0f / red[33];
            if (tid < H) rsum[tid] = 0.0f;
            __syncthreads();
            {
                float a0 = 0.0f, a1 = 0.0f, a2 = 0.0f;
                int c0 = lane, c1 = lane + 32, c2 = lane + 64;
                for (int n = w; n < len; n += 8) {
                    float a = ev[n];
                    const float* hrow = g_h + (size_t)(s0 + n) * H;
                    a0 += a * hrow[c0];
                    a1 += a * hrow[c1];
                    if (lane < 9) a2 += a * hrow[c2];
                }
                atomicAdd(&rsum[c0], a0);
                atomicAdd(&rsum[c1], a1);
                if (lane < 9) atomicAdd(&rsum[c2], a2);
            }
            __syncthreads();
            if (tid < H) rr[tid] = rsum[tid] * inv;
            __syncthreads();
        }
    }

    if (tid == 0) {
        float s = bout[0];
        for (int c = 0; c < H; c++) s += hh[c] * Wout[c];
        out[b] = s;
    }
}

// ---------------- launch ----------------
extern "C" void kernel_launch(void* const* d_in, const int* in_sizes, int n_in,
                              void* d_out, int out_size) {
    const float* nf   = (const float*)d_in[0];
    const float* ef   = (const float*)d_in[1];
    const float* Win  = (const float*)d_in[2];
    const float* bin  = (const float*)d_in[3];
    const float* W1   = (const float*)d_in[4];
    const float* b1   = (const float*)d_in[5];
    const float* W2   = (const float*)d_in[6];
    const float* b2   = (const float*)d_in[7];
    const float* gWih = (const float*)d_in[8];
    const float* gWhh = (const float*)d_in[9];
    const float* gbih = (const float*)d_in[10];
    const float* gbhh = (const float*)d_in[11];
    const float* lWih = (const float*)d_in[12];
    const float* lWhh = (const float*)d_in[13];
    const float* lbih = (const float*)d_in[14];
    const float* lbhh = (const float*)d_in[15];
    const float* Wout = (const float*)d_in[16];
    const float* bout = (const float*)d_in[17];
    const int* Esrc   = (const int*)d_in[18];
    const int* Etgt   = (const int*)d_in[19];
    const int* batch  = (const int*)d_in[20];
    float* out = (float*)d_out;

    __half *p_h16;
    cudaGetSymbolAddress((void**)&p_h16, g_h16);

    const int SMG = (128 * 168 + 160 * 136) * 2;   // 86528
    cudaFuncSetAttribute(k_gruf, cudaFuncAttributeMaxDynamicSharedMemorySize, SMG);
    size_t s2s_smem = (size_t)(2 * 292 * 73 + 292 + 292 + 4 * 73 + EVMAX + 34) * sizeof(float);
    cudaFuncSetAttribute(k_s2s, cudaFuncAttributeMaxDynamicSharedMemorySize, (int)s2s_smem);

    dim3 gT(TWP / 64, N_NODES / 128);    // 86 x 64
    dim3 gG(4, N_NODES / 128);           // 4 x 64

    k_prep<<<73 + NB_H0 + NB_RH, 256>>>(nf, Win, bin, ef, W1, b1, W2, b2);  // 0
    k_scan<<<1, 1024>>>(Esrc);                                               // 1
    k_misc<<<(160 * GGW + 255) / 256, 256>>>(Esrc, Etgt, gWih, gWhh);       // 2

    for (int t = 0; t < T_MP; t++) {
        k_tgemm<<<gT, 256>>>(p_h16);                                         // 3 (t=0)
        k_msg2<<<N_NODES, 128>>>();                                          // 4 (t=0)
        k_gruf<<<gG, 256, SMG>>>(gbih, gbhh);
    }

    k_s2s<<<NB, 256, s2s_smem>>>(lWih, lWhh, lbih, lbhh, Wout, bout, batch, out);
}

// round 16
// speedup vs baseline: 1.0168x; 1.0168x over previous
#include <cuda_runtime.h>
#include <cuda_fp16.h>
#include <math.h>

#define N_NODES 8192
#define N_EDGES 32768
#define FN 32
#define FE 16
#define H 73
#define HH (H*H)            // 5329
#define KP 80               // padded K (5 x k16)
#define TW 5402             // T2 logical row width = 73*74
#define TWP 5504            // padded pitch (43*128)
#define GGW 512             // fused GRU weight width (4 x 128)
#define NB 64
#define T_MP 3
#define T_S2S 12

// ---------------- device scratch ----------------
__device__ float g_h[N_NODES * H];
__device__ __half g_h16[N_NODES * KP];
__device__ float g_RH[N_EDGES * H];
__device__ float g_agg[N_NODES * H];
__device__ __half g_T2[(size_t)N_NODES * TWP];    // 90 MB fp16
__device__ __half g_W2e[KP * TWP];
__device__ __half g_Wgru[160 * GGW];
__device__ int g_off[N_NODES + 1];
__device__ int g_cur[N_NODES];
__device__ int g_eord[N_EDGES];
__device__ int g_tgtS[N_EDGES];

__device__ __forceinline__ float sigf(float x) { return 1.0f / (1.0f + expf(-x)); }

__device__ __forceinline__ void ldsm_x4(unsigned &r0, unsigned &r1, unsigned &r2, unsigned &r3, unsigned addr) {
    asm volatile("ldmatrix.sync.aligned.m8n8.x4.shared.b16 {%0,%1,%2,%3},[%4];"
                 : "=r"(r0), "=r"(r1), "=r"(r2), "=r"(r3) : "r"(addr));
}
__device__ __forceinline__ void ldsm_x4t(unsigned &r0, unsigned &r1, unsigned &r2, unsigned &r3, unsigned addr) {
    asm volatile("ldmatrix.sync.aligned.m8n8.x4.trans.shared.b16 {%0,%1,%2,%3},[%4];"
                 : "=r"(r0), "=r"(r1), "=r"(r2), "=r"(r3) : "r"(addr));
}
__device__ __forceinline__ void mma16816(float* d, const unsigned* a, unsigned b0, unsigned b1) {
    asm volatile("mma.sync.aligned.m16n8k16.row.col.f32.f16.f16.f32 "
                 "{%0,%1,%2,%3},{%4,%5,%6,%7},{%8,%9},{%0,%1,%2,%3};"
                 : "+f"(d[0]), "+f"(d[1]), "+f"(d[2]), "+f"(d[3])
                 : "r"(a[0]), "r"(a[1]), "r"(a[2]), "r"(a[3]), "r"(b0), "r"(b1));
}

// ---------------- k_prep: prepW2 (blocks 0..72) + h0 + RH ----------------
#define NB_H0 ((N_NODES * KP) / 256)      // 2560
#define NB_RH ((N_EDGES * H) / 256)       // 9344
__global__ __launch_bounds__(256) void k_prep(const float* __restrict__ nf,
                                              const float* __restrict__ Win,
                                              const float* __restrict__ bin,
                                              const float* __restrict__ ef,
                                              const float* __restrict__ W1,
                                              const float* __restrict__ b1,
                                              const float* __restrict__ W2,
                                              const float* __restrict__ b2) {
    __shared__ float tile[74 * 73];
    int b = blockIdx.x;
    int tid = threadIdx.x;
    if (b < 73) {
        int i = b;
        for (int idx = tid; idx < 74 * 73; idx += 256) {
            int kk = idx / 73, j = idx % 73;
            tile[idx] = (kk < H) ? W2[(size_t)kk * HH + i * H + j] : b2[i * H + j];
        }
        __syncthreads();
        for (int idx = tid; idx < 73 * 74; idx += 256) {
            int j = idx / 74, kk = idx % 74;
            g_W2e[(size_t)j * TWP + i * 74 + kk] = __float2half(tile[kk * 73 + j]);
        }
        const int PAD1 = 7 * TWP, PADT = PAD1 + 73 * 102;
        for (int p = b * 256 + tid; p < PADT; p += 73 * 256) {
            int j, c;
            if (p < PAD1) { j = 73 + p / TWP; c = p % TWP; }
            else { int q = p - PAD1; j = q / 102; c = TW + q % 102; }
            g_W2e[(size_t)j * TWP + c] = __float2half(0.0f);
        }
    } else if (b < 73 + NB_H0) {
        int idx = (b - 73) * 256 + tid;
        if (idx < N_NODES * H) g_agg[idx] = 0.0f;
        int n = idx / KP, c = idx % KP;
        if (c >= H) { g_h16[idx] = __float2half(0.0f); return; }
        const float* x = nf + n * FN;
        float acc = bin[c];
#pragma unroll
        for (int k = 0; k < FN; k++) acc += x[k] * Win[k * H + c];
        g_h[n * H + c] = acc;
        g_h16[idx] = __float2half(acc);
    } else {
        int idx = (b - 73 - NB_H0) * 256 + tid;
        int e = idx / H, c = idx % H;
        const float* x = ef + e * FE;
        float acc = b1[c];
#pragma unroll
        for (int k = 0; k < FE; k++) acc += x[k] * W1[k * H + c];
        g_RH[idx] = fmaxf(acc, 0.0f);
    }
}

// ---------------- scan with in-kernel histogram ----------------
__global__ __launch_bounds__(1024) void k_scan(const int* __restrict__ Esrc) {
    __shared__ int hist[N_NODES];
    __shared__ int sm_[1024];
    int tid = threadIdx.x;
    for (int i = tid; i < N_NODES; i += 1024) hist[i] = 0;
    __syncthreads();
    for (int e = tid; e < N_EDGES; e += 1024) atomicAdd(&hist[Esrc[e]], 1);
    __syncthreads();
    int base = tid * 8;
    int v[8], s = 0;
#pragma unroll
    for (int i = 0; i < 8; i++) { v[i] = hist[base + i]; s += v[i]; }
    sm_[tid] = s;
    __syncthreads();
    for (int off = 1; off < 1024; off <<= 1) {
        int t = (tid >= off) ? sm_[tid - off] : 0;
        __syncthreads();
        sm_[tid] += t;
        __syncthreads();
    }
    int run = sm_[tid] - s;
#pragma unroll
    for (int i = 0; i < 8; i++) {
        g_off[base + i] = run;
        g_cur[base + i] = run;
        run += v[i];
    }
    if (tid == 1023) g_off[N_NODES] = run;
}

// ---------------- misc: scatter edges + interleaved block-diag GRU weights -------
__global__ void k_misc(const int* __restrict__ Esrc, const int* __restrict__ Etgt,
                       const float* __restrict__ Wih, const float* __restrict__ Whh) {
    int idx = blockIdx.x * blockDim.x + threadIdx.x;
    if (idx < N_EDGES) {
        int p = atomicAdd(&g_cur[Esrc[idx]], 1);
        g_eord[p] = idx;
        g_tgtS[p] = Etgt[idx];
    }
    if (idx < 160 * GGW) {
        int k = idx >> 9, cc = idx & (GGW - 1);
        int t = cc >> 7, within = cc & 127;
        int j = within / 6, slot = within % 6;
        int c = 21 * t + j;
        float v = 0.0f;
        if (within < 126 && c < H) {
            if (slot == 0 && k < H)            v = Wih[(size_t)c * H + k];
            else if (slot == 2 && k < H)       v = Wih[(size_t)(H + c) * H + k];
            else if (slot == 4 && k < H)       v = Wih[(size_t)(2 * H + c) * H + k];
            else if (slot == 1 && k >= KP && k < KP + H) v = Whh[(size_t)c * H + (k - KP)];
            else if (slot == 3 && k >= KP && k < KP + H) v = Whh[(size_t)(H + c) * H + (k - KP)];
            else if (slot == 5 && k >= KP && k < KP + H) v = Whh[(size_t)(2 * H + c) * H + (k - KP)];
        }
        g_Wgru[idx] = __float2half(v);
    }
}

// ---------------- T2 GEMM: 128x64 tile, with M-block offset ----------------
__global__ __launch_bounds__(256, 3) void k_tgemm(const __half* __restrict__ A, int moff) {
    __shared__ __align__(16) __half sm_u[17024];
    __half* As = sm_u;                 // [128][88]
    __half* Bs = sm_u + 128 * 88;      // [80][72]
    __half* Cs = sm_u;                 // [128][72] alias
    int tid = threadIdx.x;
    int m0 = (moff + blockIdx.y) * 128;
    int n0 = blockIdx.x * 64;

    for (int idx = tid; idx < 1280; idx += 256) {
        int r = idx / 10, c = idx % 10;
        *reinterpret_cast<uint4*>(&As[r * 88 + c * 8]) =
            *reinterpret_cast<const uint4*>(A + (size_t)(m0 + r) * KP + c * 8);
    }
    for (int idx = tid; idx < 640; idx += 256) {
        int k = idx >> 3, c = idx & 7;
        *reinterpret_cast<uint4*>(&Bs[k * 72 + c * 8]) =
            *reinterpret_cast<const uint4*>(g_W2e + (size_t)k * TWP + n0 + c * 8);
    }
    __syncthreads();

    int wid = tid >> 5, lane = tid & 31;
    int wm0 = (wid & 3) * 32;
    int wn0 = (wid >> 2) * 32;

    float acc[2][4][4];
#pragma unroll
    for (int i = 0; i < 2; i++)
#pragma unroll
        for (int j = 0; j < 4; j++)
#pragma unroll
            for (int q = 0; q < 4; q++) acc[i][j][q] = 0.0f;

    unsigned a_base = (unsigned)__cvta_generic_to_shared(As);
    unsigned b_base = (unsigned)__cvta_generic_to_shared(Bs);
    int lr = lane & 15, lc = (lane >> 4) * 8;

#pragma unroll
    for (int ks = 0; ks < 5; ks++) {
        int k0 = ks * 16;
        unsigned af[2][4];
#pragma unroll
        for (int mi = 0; mi < 2; mi++) {
            unsigned addr = a_base + (unsigned)(((wm0 + mi * 16 + lr) * 88 + k0 + lc) * 2);
            ldsm_x4(af[mi][0], af[mi][1], af[mi][2], af[mi][3], addr);
        }
        unsigned bf[2][4];
#pragma unroll
        for (int nj = 0; nj < 2; nj++) {
            unsigned addr = b_base + (unsigned)(((k0 + lr) * 72 + wn0 + nj * 16 + lc) * 2);
            ldsm_x4t(bf[nj][0], bf[nj][1], bf[nj][2], bf[nj][3], addr);
        }
#pragma unroll
        for (int mi = 0; mi < 2; mi++)
#pragma unroll
            for (int nj = 0; nj < 2; nj++) {
                mma16816(acc[mi][2 * nj], af[mi], bf[nj][0], bf[nj][1]);
                mma16816(acc[mi][2 * nj + 1], af[mi], bf[nj][2], bf[nj][3]);
            }
    }
    __syncthreads();

    int gr = lane >> 2, gc = (lane & 3) * 2;
#pragma unroll
    for (int mi = 0; mi < 2; mi++) {
#pragma unroll
        for (int nj8 = 0; nj8 < 4; nj8++) {
            int col = wn0 + nj8 * 8 + gc;
#pragma unroll
            for (int rr = 0; rr < 2; rr++) {
                int row = wm0 + mi * 16 + gr + rr * 8;
                *reinterpret_cast<__half2*>(&Cs[row * 72 + col]) =
                    __floats2half2_rn(acc[mi][nj8][rr * 2], acc[mi][nj8][rr * 2 + 1]);
            }
        }
    }
    __syncthreads();

    for (int idx = tid; idx < 1024; idx += 256) {
        int r = idx >> 3, c = idx & 7;
        *reinterpret_cast<uint4*>(g_T2 + (size_t)(m0 + r) * TWP + n0 + c * 8) =
            *reinterpret_cast<const uint4*>(&Cs[r * 72 + c * 8]);
    }
}

// ---------------- messages: block per src (with offset) ----------------
__global__ __launch_bounds__(128) void k_msg2(int soff) {
    int src = soff + blockIdx.x;
    int s0 = g_off[src], s1 = g_off[src + 1];
    if (s0 == s1) return;
    __shared__ __align__(16) __half tvs[5408];
    __shared__ __align__(16) float rh_t[74][8];
    __shared__ int tgts[8];
    int tid = threadIdx.x;

    {
        const uint4* trow = reinterpret_cast<const uint4*>(g_T2 + (size_t)src * TWP);
        uint4* dst = reinterpret_cast<uint4*>(tvs);
        for (int q = tid; q < 676; q += 128) dst[q] = trow[q];
    }

    for (int base = s0; base < s1; base += 8) {
        int ne = min(8, s1 - base);
        for (int idx = tid; idx < 8 * 74; idx += 128) {
            int e = idx & 7, k = idx >> 3;
            float v = 0.0f;
            if (e < ne) v = (k < H) ? g_RH[(size_t)g_eord[base + e] * H + k] : 1.0f;
            rh_t[k][e] = v;
        }
        if (tid < 8) tgts[tid] = (tid < ne) ? g_tgtS[base + tid] : 0;
        __syncthreads();
        if (tid < H) {
            const __half2* tp = reinterpret_cast<const __half2*>(tvs + tid * 74);
            float a0 = 0, a1 = 0, a2 = 0, a3 = 0, a4 = 0, a5 = 0, a6 = 0, a7 = 0;
#pragma unroll
            for (int k2 = 0; k2 < 37; k2++) {
                float2 tf = __half22float2(tp[k2]);
                float4 r0a = *reinterpret_cast<const float4*>(&rh_t[2 * k2][0]);
                float4 r0b = *reinterpret_cast<const float4*>(&rh_t[2 * k2][4]);
                float4 r1a = *reinterpret_cast<const float4*>(&rh_t[2 * k2 + 1][0]);
                float4 r1b = *reinterpret_cast<const float4*>(&rh_t[2 * k2 + 1][4]);
                a0 += tf.x * r0a.x + tf.y * r1a.x;
                a1 += tf.x * r0a.y + tf.y * r1a.y;
                a2 += tf.x * r0a.z + tf.y * r1a.z;
                a3 += tf.x * r0a.w + tf.y * r1a.w;
                a4 += tf.x * r0b.x + tf.y * r1b.x;
                a5 += tf.x * r0b.y + tf.y * r1b.y;
                a6 += tf.x * r0b.z + tf.y * r1b.z;
                a7 += tf.x * r0b.w + tf.y * r1b.w;
            }
            atomicAdd(&g_agg[(size_t)tgts[0] * H + tid], a0);
            if (1 < ne) atomicAdd(&g_agg[(size_t)tgts[1] * H + tid], a1);
            if (2 < ne) atomicAdd(&g_agg[(size_t)tgts[2] * H + tid], a2);
            if (3 < ne) atomicAdd(&g_agg[(size_t)tgts[3] * H + tid], a3);
            if (4 < ne) atomicAdd(&g_agg[(size_t)tgts[4] * H + tid], a4);
            if (5 < ne) atomicAdd(&g_agg[(size_t)tgts[5] * H + tid], a5);
            if (6 < ne) atomicAdd(&g_agg[(size_t)tgts[6] * H + tid], a6);
            if (7 < ne) atomicAdd(&g_agg[(size_t)tgts[7] * H + tid], a7);
        }
        __syncthreads();
    }
}

// ---------------- fused GRU (with M-block offset) ----------------
__global__ __launch_bounds__(256) void k_gruf(const float* __restrict__ bih,
                                              const float* __restrict__ bhh, int moff) {
    extern __shared__ __half sh[];
    __half* As = sh;
    __half* Bs = sh + 128 * 168;
    float* Cs = reinterpret_cast<float*>(sh);
    int tid = threadIdx.x;
    int nt = blockIdx.x;
    int m0 = (moff + blockIdx.y) * 128;
    int n0 = nt * 128;

    for (int idx = tid; idx < 128 * KP; idx += 256) {
        int r = idx / KP, c = idx - r * KP;
        As[r * 168 + c] = __float2half((c < H) ? g_agg[(size_t)(m0 + r) * H + c] : 0.0f);
    }
    for (int idx = tid; idx < 128 * 10; idx += 256) {
        int r = idx / 10, q = idx - r * 10;
        *reinterpret_cast<uint4*>(&As[r * 168 + KP + q * 8]) =
            *reinterpret_cast<const uint4*>(g_h16 + (size_t)(m0 + r) * KP + q * 8);
    }
    for (int idx = tid; idx < 160 * 16; idx += 256) {
        int k = idx >> 4, c = idx & 15;
        *reinterpret_cast<uint4*>(&Bs[k * 136 + c * 8]) =
            *reinterpret_cast<const uint4*>(g_Wgru + (size_t)k * GGW + n0 + c * 8);
    }
    __syncthreads();

    int wid = tid >> 5, lane = tid & 31;
    int wm0 = (wid & 3) * 32;
    int wn0 = (wid >> 2) * 64;

    float acc[2][8][4];
#pragma unroll
    for (int i = 0; i < 2; i++)
#pragma unroll
        for (int j = 0; j < 8; j++)
#pragma unroll
            for (int q = 0; q < 4; q++) acc[i][j][q] = 0.0f;

    unsigned a_base = (unsigned)__cvta_generic_to_shared(As);
    unsigned b_base = (unsigned)__cvta_generic_to_shared(Bs);
    int lr = lane & 15, lc = (lane >> 4) * 8;

#pragma unroll
    for (int ks = 0; ks < 10; ks++) {
        int k0 = ks * 16;
        unsigned af[2][4];
#pragma unroll
        for (int mi = 0; mi < 2; mi++) {
            unsigned addr = a_base + (unsigned)(((wm0 + mi * 16 + lr) * 168 + k0 + lc) * 2);
            ldsm_x4(af[mi][0], af[mi][1], af[mi][2], af[mi][3], addr);
        }
        unsigned bf[4][4];
#pragma unroll
        for (int nj = 0; nj < 4; nj++) {
            unsigned addr = b_base + (unsigned)(((k0 + lr) * 136 + wn0 + nj * 16 + lc) * 2);
            ldsm_x4t(bf[nj][0], bf[nj][1], bf[nj][2], bf[nj][3], addr);
        }
#pragma unroll
        for (int mi = 0; mi < 2; mi++)
#pragma unroll
            for (int nj = 0; nj < 4; nj++) {
                mma16816(acc[mi][2 * nj], af[mi], bf[nj][0], bf[nj][1]);
                mma16816(acc[mi][2 * nj + 1], af[mi], bf[nj][2], bf[nj][3]);
            }
    }
    __syncthreads();

    int gr = lane >> 2, gc = (lane & 3) * 2;
#pragma unroll
    for (int mi = 0; mi < 2; mi++) {
#pragma unroll
        for (int nj8 = 0; nj8 < 8; nj8++) {
            int col = wn0 + nj8 * 8 + gc;
#pragma unroll
            for (int rr = 0; rr < 2; rr++) {
                int row = wm0 + mi * 16 + gr + rr * 8;
                *reinterpret_cast<float2*>(&Cs[row * 132 + col]) =
                    make_float2(acc[mi][nj8][rr * 2], acc[mi][nj8][rr * 2 + 1]);
            }
        }
    }
    __syncthreads();

    int ch0 = 21 * nt;
    int nch = min(21, H - ch0);
    for (int idx = tid; idx < 128 * nch; idx += 256) {
        int r = idx / nch, j = idx - r * nch;
        int c = ch0 + j;
        const float* gbase = &Cs[r * 132 + 6 * j];
        float ir = gbase[0], hr = gbase[1], iz = gbase[2];
        float hz = gbase[3], inn = gbase[4], hn = gbase[5];
        float rg = sigf(ir + hr + bih[c] + bhh[c]);
        float z  = sigf(iz + hz + bih[H + c] + bhh[H + c]);
        float nn = tanhf(inn + bih[2 * H + c] + rg * (hn + bhh[2 * H + c]));
        size_t n = (size_t)(m0 + r);
        float hv = (1.0f - z) * nn + z * g_h[n * H + c];
        g_h[n * H + c] = hv;
        g_h16[n * KP + c] = __float2half(hv);
        g_agg[n * H + c] = 0.0f;
    }
}

// ---------------- Set2Set ----------------
#define EVMAX 2048
__global__ __launch_bounds__(256) void k_s2s(const float* __restrict__ Wih,
                                             const float* __restrict__ Whh,
                                             const float* __restrict__ bih,
                                             const float* __restrict__ bhh,
                                             const float* __restrict__ Wout,
                                             const float* __restrict__ bout,
                                             const int* __restrict__ batch,
                                             float* __restrict__ out) {
    extern __shared__ float sm[];
    float* Wa    = sm;
    float* Wb    = Wa + 292 * 73;
    float* bias  = Wb + 292 * 73;
    float* gates = bias + 292;
    float* hh    = gates + 292;
    float* cc    = hh + 73;
    float* rr    = cc + 73;
    float* rsum  = rr + 73;
    float* ev    = rsum + 73;
    float* red   = ev + EVMAX;

    int tid = threadIdx.x;
    int b = blockIdx.x;

    for (int i = tid; i < 292 * 73; i += 256) {
        int g = i / 73, k = i % 73;
        Wa[i] = Wih[(size_t)g * 146 + k] + Whh[(size_t)g * 73 + k];
        Wb[i] = Wih[(size_t)g * 146 + 73 + k];
    }
    for (int i = tid; i < 292; i += 256) bias[i] = bih[i] + bhh[i];
    if (tid < H) { hh[tid] = 0.0f; cc[tid] = 0.0f; rr[tid] = 0.0f; }

    int lo = 0, hi = N_NODES;
    while (lo < hi) { int mid = (lo + hi) >> 1; if (batch[mid] < b) lo = mid + 1; else hi = mid; }
    int s0 = lo;
    hi = N_NODES;
    while (lo < hi) { int mid = (lo + hi) >> 1; if (batch[mid] < b + 1) lo = mid + 1; else hi = mid; }
    int len = lo - s0;
    if (len > EVMAX) len = EVMAX;
    __syncthreads();

    int lane = tid & 31, w = tid >> 5;

    for (int t = 0; t < T_S2S; t++) {
        for (int g = tid; g < 292; g += 256) {
            const float* wa = Wa + g * 73;
            const float* wb = Wb + g * 73;
            float acc = bias[g];
            for (int k = 0; k < H; k++) acc += hh[k] * wa[k] + rr[k] * wb[k];
            gates[g] = acc;
        }
        __syncthreads();
        if (tid < H) {
            float ig = gates[tid], fg = gates[H + tid], gg = gates[2 * H + tid], og = gates[3 * H + tid];
            float c2 = sigf(fg) * cc[tid] + sigf(ig) * tanhf(gg);
            cc[tid] = c2;
            hh[tid] = sigf(og) * tanhf(c2);
        }
        __syncthreads();

        if (len > 0) {
            for (int n = w; n < len; n += 8) {
                const float* hrow = g_h + (size_t)(s0 + n) * H;
                float acc = 0.0f;
                for (int c = lane; c < H; c += 32) acc += hrow[c] * hh[c];
#pragma unroll
                for (int o = 16; o; o >>= 1) acc += __shfl_down_sync(0xffffffffu, acc, o);
                if (lane == 0) ev[n] = acc;
            }
            __syncthreads();
            float m = -INFINITY;
            for (int n = tid; n < len; n += 256) m = fmaxf(m, ev[n]);
#pragma unroll
            for (int o = 16; o; o >>= 1) m = fmaxf(m, __shfl_xor_sync(0xffffffffu, m, o));
            if (lane == 0) red[w] = m;
            __syncthreads();
            if (tid == 0) {
                float mm = red[0];
                for (int i = 1; i < 8; i++) mm = fmaxf(mm, red[i]);
                red[32] = mm;
            }
            __syncthreads();
            m = red[32];
            float s = 0.0f;
            for (int n = tid; n < len; n += 256) { float a = expf(ev[n] - m); ev[n] = a; s += a; }
#pragma unroll
            for (int o = 16; o; o >>= 1) s += __shfl_xor_sync(0xffffffffu, s, o);
            if (lane == 0) red[w] = s;
            __syncthreads();
            if (tid == 0) {
                float ss = 0.0f;
                for (int i = 0; i < 8; i++) ss += red[i];
                red[33] = ss;
            }
            __syncthreads();
            float inv = 1.0f / red[33];
            if (tid < H) rsum[tid] = 0.0f;
            __syncthreads();
            {
                float a0 = 0.0f, a1 = 0.0f, a2 = 0.0f;
                int c0 = lane, c1 = lane + 32, c2 = lane + 64;
                for (int n = w; n < len; n += 8) {
                    float a = ev[n];
                    const float* hrow = g_h + (size_t)(s0 + n) * H;
                    a0 += a * hrow[c0];
                    a1 += a * hrow[c1];
                    if (lane < 9) a2 += a * hrow[c2];
                }
                atomicAdd(&rsum[c0], a0);
                atomicAdd(&rsum[c1], a1);
                if (lane < 9) atomicAdd(&rsum[c2], a2);
            }
            __syncthreads();
            if (tid < H) rr[tid] = rsum[tid] * inv;
            __syncthreads();
        }
    }

    if (tid == 0) {
        float s = bout[0];
        for (int c = 0; c < H; c++) s += hh[c] * Wout[c];
        out[b] = s;
    }
}

// ---------------- launch (two-stream half pipelines) ----------------
static cudaStream_t g_s2 = 0;
static cudaEvent_t g_evF, g_mA[T_MP], g_mB[T_MP], g_gA[T_MP], g_gB[T_MP], g_evEnd;
static bool g_init_done = false;

extern "C" void kernel_launch(void* const* d_in, const int* in_sizes, int n_in,
                              void* d_out, int out_size) {
    const float* nf   = (const float*)d_in[0];
    const float* ef   = (const float*)d_in[1];
    const float* Win  = (const float*)d_in[2];
    const float* bin  = (const float*)d_in[3];
    const float* W1   = (const float*)d_in[4];
    const float* b1   = (const float*)d_in[5];
    const float* W2   = (const float*)d_in[6];
    const float* b2   = (const float*)d_in[7];
    const float* gWih = (const float*)d_in[8];
    const float* gWhh = (const float*)d_in[9];
    const float* gbih = (const float*)d_in[10];
    const float* gbhh = (const float*)d_in[11];
    const float* lWih = (const float*)d_in[12];
    const float* lWhh = (const float*)d_in[13];
    const float* lbih = (const float*)d_in[14];
    const float* lbhh = (const float*)d_in[15];
    const float* Wout = (const float*)d_in[16];
    const float* bout = (const float*)d_in[17];
    const int* Esrc   = (const int*)d_in[18];
    const int* Etgt   = (const int*)d_in[19];
    const int* batch  = (const int*)d_in[20];
    float* out = (float*)d_out;

    if (!g_init_done) {
        cudaStreamCreateWithFlags(&g_s2, cudaStreamNonBlocking);
        cudaEventCreateWithFlags(&g_evF, cudaEventDisableTiming);
        cudaEventCreateWithFlags(&g_evEnd, cudaEventDisableTiming);
        for (int t = 0; t < T_MP; t++) {
            cudaEventCreateWithFlags(&g_mA[t], cudaEventDisableTiming);
            cudaEventCreateWithFlags(&g_mB[t], cudaEventDisableTiming);
            cudaEventCreateWithFlags(&g_gA[t], cudaEventDisableTiming);
            cudaEventCreateWithFlags(&g_gB[t], cudaEventDisableTiming);
        }
        g_init_done = true;
    }

    __half *p_h16;
    cudaGetSymbolAddress((void**)&p_h16, g_h16);

    const int SMG = (128 * 168 + 160 * 136) * 2;   // 86528
    cudaFuncSetAttribute(k_gruf, cudaFuncAttributeMaxDynamicSharedMemorySize, SMG);
    size_t s2s_smem = (size_t)(2 * 292 * 73 + 292 + 292 + 4 * 73 + EVMAX + 34) * sizeof(float);
    cudaFuncSetAttribute(k_s2s, cudaFuncAttributeMaxDynamicSharedMemorySize, (int)s2s_smem);

    dim3 gT(TWP / 64, 32);    // half of M
    dim3 gG(4, 32);           // half of M

    // prologue on the main stream
    k_prep<<<73 + NB_H0 + NB_RH, 256>>>(nf, Win, bin, ef, W1, b1, W2, b2);
    k_scan<<<1, 1024>>>(Esrc);
    k_misc<<<(160 * GGW + 255) / 256, 256>>>(Esrc, Etgt, gWih, gWhh);

    // fork s2 from the main stream
    cudaEventRecord(g_evF, 0);
    cudaStreamWaitEvent(g_s2, g_evF, 0);

    for (int t = 0; t < T_MP; t++) {
        // half A on main stream, half B on s2
        k_tgemm<<<gT, 256, 0, 0>>>(p_h16, 0);
        k_tgemm<<<gT, 256, 0, g_s2>>>(p_h16, 32);

        // msg2(t) must see both gruf halves of step t-1 (agg rows zeroed)
        if (t > 0) {
            cudaStreamWaitEvent(0, g_gB[t - 1], 0);
            cudaStreamWaitEvent(g_s2, g_gA[t - 1], 0);
        }
        k_msg2<<<4096, 128, 0, 0>>>(0);
        k_msg2<<<4096, 128, 0, g_s2>>>(4096);
        cudaEventRecord(g_mA[t], 0);
        cudaEventRecord(g_mB[t], g_s2);

        // gruf needs ALL messages accumulated
        cudaStreamWaitEvent(0, g_mB[t], 0);
        cudaStreamWaitEvent(g_s2, g_mA[t], 0);
        k_gruf<<<gG, 256, SMG, 0>>>(gbih, gbhh, 0);
        k_gruf<<<gG, 256, SMG, g_s2>>>(gbih, gbhh, 32);
        cudaEventRecord(g_gA[t], 0);
        cudaEventRecord(g_gB[t], g_s2);
    }

    // join s2 back into the main stream
    cudaEventRecord(g_evEnd, g_s2);
    cudaStreamWaitEvent(0, g_evEnd, 0);

    k_s2s<<<NB, 256, s2s_smem>>>(lWih, lWhh, lbih, lbhh, Wout, bout, batch, out);
}